// round 1
// baseline (speedup 1.0000x reference)
#include <cuda_runtime.h>
#include <math.h>

// ---------------- problem constants ----------------
#define D_   1024
#define H_   16
#define DH_  64
#define NL_  4
#define DFF_ 4096
#define V_   32000
#define S_   1024
#define NB_  2
#define BSZ_ (NB_*S_)   // 2048 rows of activations

static inline int cdiv(int a, int b) { return (a + b - 1) / b; }

// ---------------- scratch (no allocation allowed) ----------------
__device__ float g_x  [BSZ_*D_];          // residual stream
__device__ float g_h  [BSZ_*D_];          // LN output
__device__ float g_q  [BSZ_*D_];
__device__ float g_k  [BSZ_*D_];
__device__ float g_v  [BSZ_*D_];
__device__ float g_o  [BSZ_*D_];          // attn output (pre O-proj)
__device__ float g_ff [BSZ_*DFF_];        // FFN intermediate
__device__ float g_att[(size_t)NB_*H_*S_*S_];   // scores / softmax weights (~134MB)
__device__ float g_wq [NL_*D_*D_];        // repacked [L, D, H*DH]
__device__ float g_wk [NL_*D_*D_];
__device__ float g_wv [NL_*D_*D_];

// ---------------- repack QKV weights: [L,H,D,DH] -> [L,D,H*DH] ----------------
__global__ void repack_k(const float* __restrict__ wq,
                         const float* __restrict__ wk,
                         const float* __restrict__ wv) {
    int i = blockIdx.x * blockDim.x + threadIdx.x;     // dst-linear index
    if (i >= NL_*D_*D_) return;
    int e = i & 63;
    int h = (i >> 6) & 15;
    int d = (i >> 10) & 1023;
    int l = i >> 20;
    size_t src = (((size_t)(l*H_ + h) * D_ + d) * DH_) + e;
    g_wq[i] = wq[src];
    g_wk[i] = wk[src];
    g_wv[i] = wv[src];
}

// ---------------- embedding + sinusoidal PE ----------------
__global__ void embed_k(const int* __restrict__ idx, const float* __restrict__ emb) {
    int t = blockIdx.x * blockDim.x + threadIdx.x;     // over BSZ_*D_
    if (t >= BSZ_*D_) return;
    int d  = t & (D_-1);
    int bs = t >> 10;
    int s  = bs & (S_-1);
    int tok = idx[bs];
    int i2 = d & ~1;                                   // even dim index 2i
    float freq = __expf((float)i2 * (-9.210340371976184f / (float)D_)); // -ln(10000)/D
    float ang  = (float)s * freq;
    float pe   = (d & 1) ? cosf(ang) : sinf(ang);
    g_x[t] = emb[(size_t)tok * D_ + d] * 32.0f + pe;   // sqrt(1024)=32
}

// ---------------- layernorm (one block per row) ----------------
__global__ void ln_k(const float* __restrict__ in, float* __restrict__ out,
                     const float* __restrict__ sc, const float* __restrict__ bi) {
    int row = blockIdx.x;
    const float* x = in + (size_t)row * D_;
    int tid = threadIdx.x;
    float s = 0.f, ss = 0.f;
    for (int i = tid; i < D_; i += 256) { float v = x[i]; s += v; ss = fmaf(v, v, ss); }
    __shared__ float rs[8], rq[8];
    #pragma unroll
    for (int o = 16; o > 0; o >>= 1) {
        s  += __shfl_xor_sync(0xffffffffu, s,  o);
        ss += __shfl_xor_sync(0xffffffffu, ss, o);
    }
    if ((tid & 31) == 0) { rs[tid >> 5] = s; rq[tid >> 5] = ss; }
    __syncthreads();
    if (tid < 32) {
        float a = (tid < 8) ? rs[tid] : 0.f;
        float b = (tid < 8) ? rq[tid] : 0.f;
        #pragma unroll
        for (int o = 4; o > 0; o >>= 1) {
            a += __shfl_xor_sync(0xffffffffu, a, o);
            b += __shfl_xor_sync(0xffffffffu, b, o);
        }
        if (tid == 0) { rs[0] = a; rq[0] = b; }
    }
    __syncthreads();
    float mean = rs[0] * (1.0f / D_);
    float var  = rq[0] * (1.0f / D_) - mean * mean;
    float inv  = rsqrtf(var + 1e-5f);
    for (int i = tid; i < D_; i += 256)
        out[(size_t)row * D_ + i] = (x[i] - mean) * inv * sc[i] + bi[i];
}

// ---------------- causal softmax over score rows, zero the masked tail ----------------
__global__ void softmax_k(float* __restrict__ att) {
    size_t row = blockIdx.x;                 // (b*H + h)*S + i
    int i = (int)(row & (S_-1));
    float* p = att + row * (size_t)S_;
    int n = i + 1;
    int tid = threadIdx.x;
    __shared__ float red[8];

    float m = -3.4e38f;
    for (int j = tid; j < n; j += 256) m = fmaxf(m, p[j]);
    #pragma unroll
    for (int o = 16; o > 0; o >>= 1) m = fmaxf(m, __shfl_xor_sync(0xffffffffu, m, o));
    if ((tid & 31) == 0) red[tid >> 5] = m;
    __syncthreads();
    if (tid < 32) {
        float t = (tid < 8) ? red[tid] : -3.4e38f;
        #pragma unroll
        for (int o = 4; o > 0; o >>= 1) t = fmaxf(t, __shfl_xor_sync(0xffffffffu, t, o));
        if (tid == 0) red[0] = t;
    }
    __syncthreads();
    m = red[0];

    float sum = 0.f;
    for (int j = tid; j < n; j += 256) { float e = __expf(p[j] - m); p[j] = e; sum += e; }
    __syncthreads();
    #pragma unroll
    for (int o = 16; o > 0; o >>= 1) sum += __shfl_xor_sync(0xffffffffu, sum, o);
    if ((tid & 31) == 0) red[tid >> 5] = sum;
    __syncthreads();
    if (tid < 32) {
        float t = (tid < 8) ? red[tid] : 0.f;
        #pragma unroll
        for (int o = 4; o > 0; o >>= 1) t += __shfl_xor_sync(0xffffffffu, t, o);
        if (tid == 0) red[0] = t;
    }
    __syncthreads();
    float inv = 1.0f / red[0];
    for (int j = tid; j < n; j += 256) p[j] *= inv;
    for (int j = n + tid; j < S_; j += 256) p[j] = 0.f;   // zero masked tail -> P@V can use full K
}

// ---------------- generic tiled SGEMM ----------------
// C[z] = alpha * A[z] @ op(B[z]) (+bias) (+Cin) (relu), op = transpose if TRANSB
// batched via grid.z with z -> (zb, zh) = (z/nzh, z%nzh) strides.
constexpr int BM = 128, BN = 128, BK = 16, TM = 8, TN = 8;

template<bool TRANSB, bool RELU, bool RESID, bool BIAS>
__global__ void __launch_bounds__(256) gemm_k(
    const float* __restrict__ Ag, const float* __restrict__ Bg,
    const float* __restrict__ biasg, const float* __restrict__ Cing,
    float* __restrict__ Cg,
    int M, int N, int K, int lda, int ldb, int ldc,
    int nzh, long sAb, long sAh, long sBb, long sBh, long sCb, long sCh,
    float alpha)
{
    int z  = blockIdx.z;
    int zb = z / nzh, zh = z % nzh;
    const float* A   = Ag + zb * sAb + zh * sAh;
    const float* Bp  = Bg + zb * sBb + zh * sBh;
    float*       C   = Cg + zb * sCb + zh * sCh;
    const float* Cin = RESID ? (Cing + zb * sCb + zh * sCh) : nullptr;

    __shared__ float As[BK][BM + 4];
    __shared__ float Bs[BK][BN + 4];

    int tid  = threadIdx.x;
    int row0 = blockIdx.y * BM;
    int col0 = blockIdx.x * BN;
    int ty = tid >> 4, tx = tid & 15;

    float acc[TM][TN] = {};

    for (int k0 = 0; k0 < K; k0 += BK) {
        // A tile: 128 x 16 (transpose into SMEM), float4 along K
        #pragma unroll
        for (int r = 0; r < 2; r++) {
            int idx = tid + r * 256;
            int m   = idx >> 2;
            int kg  = (idx & 3) * 4;
            int gm  = row0 + m;
            float4 v = make_float4(0.f, 0.f, 0.f, 0.f);
            if (gm < M)
                v = *reinterpret_cast<const float4*>(&A[(size_t)gm * lda + k0 + kg]);
            As[kg+0][m] = v.x; As[kg+1][m] = v.y; As[kg+2][m] = v.z; As[kg+3][m] = v.w;
        }
        // B tile: 16 x 128
        if (!TRANSB) {
            #pragma unroll
            for (int r = 0; r < 2; r++) {
                int idx = tid + r * 256;
                int k   = idx >> 5;
                int n   = (idx & 31) * 4;
                int gn  = col0 + n;
                float4 v = make_float4(0.f, 0.f, 0.f, 0.f);
                if (gn < N)
                    v = *reinterpret_cast<const float4*>(&Bp[(size_t)(k0 + k) * ldb + gn]);
                *reinterpret_cast<float4*>(&Bs[k][n]) = v;
            }
        } else {
            #pragma unroll
            for (int r = 0; r < 2; r++) {
                int idx = tid + r * 256;
                int n   = idx >> 2;
                int kg  = (idx & 3) * 4;
                int gn  = col0 + n;
                float4 v = make_float4(0.f, 0.f, 0.f, 0.f);
                if (gn < N)
                    v = *reinterpret_cast<const float4*>(&Bp[(size_t)gn * ldb + k0 + kg]);
                Bs[kg+0][n] = v.x; Bs[kg+1][n] = v.y; Bs[kg+2][n] = v.z; Bs[kg+3][n] = v.w;
            }
        }
        __syncthreads();

        #pragma unroll
        for (int kk = 0; kk < BK; kk++) {
            float a[TM], b[TN];
            #pragma unroll
            for (int i = 0; i < TM; i++) a[i] = As[kk][ty * TM + i];
            #pragma unroll
            for (int j = 0; j < TN; j++) b[j] = Bs[kk][tx * TN + j];
            #pragma unroll
            for (int i = 0; i < TM; i++)
                #pragma unroll
                for (int j = 0; j < TN; j++)
                    acc[i][j] = fmaf(a[i], b[j], acc[i][j]);
        }
        __syncthreads();
    }

    #pragma unroll
    for (int i = 0; i < TM; i++) {
        int gm = row0 + ty * TM + i;
        if (gm >= M) continue;
        #pragma unroll
        for (int j = 0; j < TN; j++) {
            int gn = col0 + tx * TN + j;
            if (gn >= N) continue;
            float v = acc[i][j] * alpha;
            if (BIAS)  v += biasg[gn];
            if (RESID) v += Cin[(size_t)gm * ldc + gn];
            if (RELU)  v = fmaxf(v, 0.f);
            C[(size_t)gm * ldc + gn] = v;
        }
    }
}

template<bool TB, bool RELU, bool RESID, bool BIAS>
static void launch_gemm(const float* A, const float* Bm, const float* bias,
                        const float* Cin, float* C,
                        int M, int N, int K, int lda, int ldb, int ldc,
                        float alpha = 1.f, int Z = 1, int nzh = 1,
                        long sAb = 0, long sAh = 0, long sBb = 0, long sBh = 0,
                        long sCb = 0, long sCh = 0)
{
    dim3 grid(cdiv(N, BN), cdiv(M, BM), Z);
    gemm_k<TB, RELU, RESID, BIAS><<<grid, 256>>>(
        A, Bm, bias, Cin, C, M, N, K, lda, ldb, ldc,
        nzh, sAb, sAh, sBb, sBh, sCb, sCh, alpha);
}

// ---------------- orchestration ----------------
extern "C" void kernel_launch(void* const* d_in, const int* in_sizes, int n_in,
                              void* d_out, int out_size) {
    const int*   idx   = (const int*)  d_in[0];
    const float* emb   = (const float*)d_in[1];
    const float* cls_b = (const float*)d_in[2];
    const float* ln1_s = (const float*)d_in[3];
    const float* ln1_b = (const float*)d_in[4];
    const float* wq    = (const float*)d_in[5];
    const float* bq    = (const float*)d_in[6];
    const float* wk    = (const float*)d_in[7];
    const float* bk    = (const float*)d_in[8];
    const float* wv    = (const float*)d_in[9];
    const float* bv    = (const float*)d_in[10];
    const float* wo    = (const float*)d_in[11];
    const float* bo    = (const float*)d_in[12];
    const float* ln2_s = (const float*)d_in[13];
    const float* ln2_b = (const float*)d_in[14];
    const float* w1    = (const float*)d_in[15];
    const float* b1    = (const float*)d_in[16];
    const float* w2    = (const float*)d_in[17];
    const float* b2    = (const float*)d_in[18];
    const float* lnf_s = (const float*)d_in[19];
    const float* lnf_b = (const float*)d_in[20];
    float* out = (float*)d_out;

    float *gx, *gh, *gq, *gk, *gv, *go, *gff, *gatt, *gwq, *gwk, *gwv;
    cudaGetSymbolAddress((void**)&gx,  g_x);
    cudaGetSymbolAddress((void**)&gh,  g_h);
    cudaGetSymbolAddress((void**)&gq,  g_q);
    cudaGetSymbolAddress((void**)&gk,  g_k);
    cudaGetSymbolAddress((void**)&gv,  g_v);
    cudaGetSymbolAddress((void**)&go,  g_o);
    cudaGetSymbolAddress((void**)&gff, g_ff);
    cudaGetSymbolAddress((void**)&gatt,g_att);
    cudaGetSymbolAddress((void**)&gwq, g_wq);
    cudaGetSymbolAddress((void**)&gwk, g_wk);
    cudaGetSymbolAddress((void**)&gwv, g_wv);

    repack_k<<<cdiv(NL_*D_*D_, 256), 256>>>(wq, wk, wv);
    embed_k <<<cdiv(BSZ_*D_,   256), 256>>>(idx, emb);

    const long sQ  = (long)S_ * D_;      // batch stride for q/k/v/o (per b)
    const long sAT = (long)H_ * S_ * S_; // att batch stride (per b)

    for (int l = 0; l < NL_; l++) {
        ln_k<<<BSZ_, 256>>>(gx, gh, ln1_s + l*D_, ln1_b + l*D_);

        launch_gemm<false,false,false,true>(gh, gwq + (size_t)l*D_*D_, bq + l*D_, nullptr, gq,
                                            BSZ_, D_, D_, D_, D_, D_);
        launch_gemm<false,false,false,true>(gh, gwk + (size_t)l*D_*D_, bk + l*D_, nullptr, gk,
                                            BSZ_, D_, D_, D_, D_, D_);
        launch_gemm<false,false,false,true>(gh, gwv + (size_t)l*D_*D_, bv + l*D_, nullptr, gv,
                                            BSZ_, D_, D_, D_, D_, D_);

        // scores[b,h] = 1/8 * q[b,h] @ k[b,h]^T   (M=N=1024, K=64)
        launch_gemm<true,false,false,false>(gq, gk, nullptr, nullptr, gatt,
                                            S_, S_, DH_, D_, D_, S_,
                                            0.125f, NB_*H_, H_,
                                            sQ, DH_, sQ, DH_, sAT, (long)S_*S_);

        softmax_k<<<NB_*H_*S_, 256>>>(gatt);

        // o[b,h] = P[b,h] @ v[b,h]   (M=1024, N=64, K=1024)
        launch_gemm<false,false,false,false>(gatt, gv, nullptr, nullptr, go,
                                             S_, DH_, S_, S_, D_, D_,
                                             1.f, NB_*H_, H_,
                                             sAT, (long)S_*S_, sQ, DH_, sQ, DH_);

        // x += o @ wo + bo
        launch_gemm<false,false,true,true>(go, wo + (size_t)l*D_*D_, bo + l*D_, gx, gx,
                                           BSZ_, D_, D_, D_, D_, D_);

        ln_k<<<BSZ_, 256>>>(gx, gh, ln2_s + l*D_, ln2_b + l*D_);

        // ff = relu(h @ w1 + b1)
        launch_gemm<false,true,false,true>(gh, w1 + (size_t)l*D_*DFF_, b1 + l*DFF_, nullptr, gff,
                                           BSZ_, DFF_, D_, D_, DFF_, DFF_);
        // x += ff @ w2 + b2
        launch_gemm<false,false,true,true>(gff, w2 + (size_t)l*DFF_*D_, b2 + l*D_, gx, gx,
                                           BSZ_, D_, DFF_, DFF_, D_, D_);
    }

    ln_k<<<BSZ_, 256>>>(gx, gh, lnf_s, lnf_b);

    // logits = h @ emb^T + cls_b   (M=2048, N=32000, K=1024)
    launch_gemm<true,false,false,true>(gh, emb, cls_b, nullptr, out,
                                       BSZ_, V_, D_, D_, D_, V_);
}

// round 3
// speedup vs baseline: 2.8664x; 2.8664x over previous
#include <cuda_runtime.h>
#include <math.h>
#include <cstdint>

// ---------------- problem constants ----------------
#define D_   1024
#define H_   16
#define DH_  64
#define NL_  4
#define DFF_ 4096
#define V_   32000
#define S_   1024
#define NB_  2
#define BSZ_ (NB_*S_)

static inline int cdiv(int a, int b) { return (a + b - 1) / b; }

// ---------------- scratch ----------------
__device__ float g_x   [BSZ_*D_];
__device__ float g_h   [BSZ_*D_];
__device__ float g_qkv [BSZ_*3*D_];
__device__ float g_o   [BSZ_*D_];
__device__ float g_ff  [BSZ_*DFF_];
__device__ float g_att [(size_t)NB_*H_*S_*S_];
__device__ float g_vT  [(size_t)NB_*H_*DH_*S_];
__device__ float g_wqkv[(size_t)NL_*3*D_*D_];
__device__ float g_woT [(size_t)NL_*D_*D_];
__device__ float g_w1T [(size_t)NL_*DFF_*D_];
__device__ float g_w2T [(size_t)NL_*D_*DFF_];
__device__ float g_bqkv[NL_*3*D_];

// ---------------- tf32 helpers ----------------
__device__ __forceinline__ float tf32r(float x) {
    uint32_t u;
    asm("cvt.rna.tf32.f32 %0, %1;" : "=r"(u) : "f"(x));
    return __uint_as_float(u);
}

__device__ __forceinline__ void mma1688(float* d, const uint32_t* a, const uint32_t* b) {
    asm volatile(
        "mma.sync.aligned.m16n8k8.row.col.f32.tf32.tf32.f32 "
        "{%0,%1,%2,%3}, {%4,%5,%6,%7}, {%8,%9}, {%0,%1,%2,%3};"
        : "+f"(d[0]), "+f"(d[1]), "+f"(d[2]), "+f"(d[3])
        : "r"(a[0]), "r"(a[1]), "r"(a[2]), "r"(a[3]), "r"(b[0]), "r"(b[1]));
}

// ============ tf32 mma.sync GEMM ============
// C = alpha * A @ B^T (+bias)(+Cin)(relu); A [M,K] row-major, B [N,K] K-major.
constexpr int BM = 128, BN = 128, BK = 32, BKP = 36;

template<bool RELU, bool RESID, bool BIAS, bool CAUSAL>
__global__ void __launch_bounds__(256) gemm_mma(
    const float* __restrict__ Ag, const float* __restrict__ Bg,
    const float* __restrict__ biasg, const float* __restrict__ Cing,
    float* __restrict__ Cg,
    int M, int N, int K, int lda, int ldb, int ldc,
    int nz2, long sA1, long sA2, long sB1, long sB2, long sC1, long sC2,
    float alpha)
{
    int row0 = blockIdx.y * BM;
    int col0 = blockIdx.x * BN;
    if (CAUSAL && col0 > row0 + BM - 1) return;

    int z = blockIdx.z, z1 = z / nz2, z2 = z - z1 * nz2;
    const float* A   = Ag + z1 * sA1 + z2 * sA2;
    const float* B   = Bg + z1 * sB1 + z2 * sB2;
    float*       C   = Cg + z1 * sC1 + z2 * sC2;
    const float* Cin = RESID ? (Cing + z1 * sC1 + z2 * sC2) : nullptr;

    __shared__ float As[BM][BKP];
    __shared__ float Bs[BN][BKP];

    int tid = threadIdx.x;
    int wid = tid >> 5, lane = tid & 31;
    int wm = wid >> 2, wn = wid & 3;        // warp tile: 64x32
    int gid = lane >> 2, tig = lane & 3;

    float acc[4][4][4];
    #pragma unroll
    for (int a = 0; a < 4; a++)
        #pragma unroll
        for (int b = 0; b < 4; b++)
            #pragma unroll
            for (int c = 0; c < 4; c++) acc[a][b][c] = 0.f;

    int KT = K / BK;
    float4 pa[4], pb[4];

    // preload chunk 0
    #pragma unroll
    for (int j = 0; j < 4; j++) {
        int idx = tid + j * 256;
        int r = idx >> 3, c4 = (idx & 7) * 4;
        int gm = row0 + r;
        pa[j] = (gm < M) ? *(const float4*)(A + (size_t)gm * lda + c4)
                         : make_float4(0.f, 0.f, 0.f, 0.f);
        int gn = col0 + r;
        pb[j] = (gn < N) ? *(const float4*)(B + (size_t)gn * ldb + c4)
                         : make_float4(0.f, 0.f, 0.f, 0.f);
    }

    for (int kt = 0; kt < KT; kt++) {
        // stage current chunk into smem (tf32-rounded)
        #pragma unroll
        for (int j = 0; j < 4; j++) {
            int idx = tid + j * 256;
            int r = idx >> 3, c4 = (idx & 7) * 4;
            As[r][c4+0] = tf32r(pa[j].x); As[r][c4+1] = tf32r(pa[j].y);
            As[r][c4+2] = tf32r(pa[j].z); As[r][c4+3] = tf32r(pa[j].w);
            Bs[r][c4+0] = tf32r(pb[j].x); Bs[r][c4+1] = tf32r(pb[j].y);
            Bs[r][c4+2] = tf32r(pb[j].z); Bs[r][c4+3] = tf32r(pb[j].w);
        }
        __syncthreads();

        // prefetch next chunk
        if (kt + 1 < KT) {
            int k0 = (kt + 1) * BK;
            #pragma unroll
            for (int j = 0; j < 4; j++) {
                int idx = tid + j * 256;
                int r = idx >> 3, c4 = (idx & 7) * 4;
                int gm = row0 + r;
                pa[j] = (gm < M) ? *(const float4*)(A + (size_t)gm * lda + k0 + c4)
                                 : make_float4(0.f, 0.f, 0.f, 0.f);
                int gn = col0 + r;
                pb[j] = (gn < N) ? *(const float4*)(B + (size_t)gn * ldb + k0 + c4)
                                 : make_float4(0.f, 0.f, 0.f, 0.f);
            }
        }

        // compute: 4 k-steps of 8
        #pragma unroll
        for (int ks = 0; ks < 4; ks++) {
            uint32_t af[4][4], bf[4][2];
            int kc = ks * 8 + tig;
            #pragma unroll
            for (int mt = 0; mt < 4; mt++) {
                int br = wm * 64 + mt * 16 + gid;
                af[mt][0] = __float_as_uint(As[br    ][kc    ]);
                af[mt][1] = __float_as_uint(As[br + 8][kc    ]);
                af[mt][2] = __float_as_uint(As[br    ][kc + 4]);
                af[mt][3] = __float_as_uint(As[br + 8][kc + 4]);
            }
            #pragma unroll
            for (int nt = 0; nt < 4; nt++) {
                int bn = wn * 32 + nt * 8 + gid;
                bf[nt][0] = __float_as_uint(Bs[bn][kc    ]);
                bf[nt][1] = __float_as_uint(Bs[bn][kc + 4]);
            }
            #pragma unroll
            for (int mt = 0; mt < 4; mt++)
                #pragma unroll
                for (int nt = 0; nt < 4; nt++)
                    mma1688(acc[mt][nt], af[mt], bf[nt]);
        }
        __syncthreads();
    }

    // ---------------- epilogue ----------------
    #pragma unroll
    for (int mt = 0; mt < 4; mt++) {
        #pragma unroll
        for (int half = 0; half < 2; half++) {
            int gm = row0 + wm * 64 + mt * 16 + gid + half * 8;
            if (gm >= M) continue;
            #pragma unroll
            for (int nt = 0; nt < 4; nt++) {
                int gn = col0 + wn * 32 + nt * 8 + 2 * tig;
                if (gn >= N) continue;
                float v0 = acc[mt][nt][half * 2 + 0] * alpha;
                float v1 = acc[mt][nt][half * 2 + 1] * alpha;
                if (BIAS)  { v0 += biasg[gn]; v1 += biasg[gn + 1]; }
                if (RESID) {
                    const float* ci = Cin + (size_t)gm * ldc + gn;
                    v0 += ci[0]; v1 += ci[1];
                }
                if (RELU) { v0 = fmaxf(v0, 0.f); v1 = fmaxf(v1, 0.f); }
                float2* cp = (float2*)(C + (size_t)gm * ldc + gn);
                *cp = make_float2(v0, v1);
            }
        }
    }
}

// ============ auxiliary kernels ============
__global__ void embed_k(const int* __restrict__ idx, const float* __restrict__ emb) {
    int t = blockIdx.x * blockDim.x + threadIdx.x;
    if (t >= BSZ_ * D_) return;
    int d = t & (D_ - 1);
    int bs = t >> 10;
    int s = bs & (S_ - 1);
    int tok = idx[bs];
    int i2 = d & ~1;
    float freq = __expf((float)i2 * (-9.210340371976184f / (float)D_));
    float ang = (float)s * freq;
    float pe = (d & 1) ? cosf(ang) : sinf(ang);
    g_x[t] = emb[(size_t)tok * D_ + d] * 32.0f + pe;
}

__global__ void ln_k(const float* __restrict__ in, float* __restrict__ out,
                     const float* __restrict__ sc, const float* __restrict__ bi) {
    int row = blockIdx.x;
    const float* x = in + (size_t)row * D_;
    int tid = threadIdx.x;
    float s = 0.f, ss = 0.f;
    for (int i = tid; i < D_; i += 256) { float v = x[i]; s += v; ss = fmaf(v, v, ss); }
    __shared__ float rs[8], rq[8];
    #pragma unroll
    for (int o = 16; o > 0; o >>= 1) {
        s  += __shfl_xor_sync(0xffffffffu, s,  o);
        ss += __shfl_xor_sync(0xffffffffu, ss, o);
    }
    if ((tid & 31) == 0) { rs[tid >> 5] = s; rq[tid >> 5] = ss; }
    __syncthreads();
    if (tid < 32) {
        float a = (tid < 8) ? rs[tid] : 0.f;
        float b = (tid < 8) ? rq[tid] : 0.f;
        #pragma unroll
        for (int o = 4; o > 0; o >>= 1) {
            a += __shfl_xor_sync(0xffffffffu, a, o);
            b += __shfl_xor_sync(0xffffffffu, b, o);
        }
        if (tid == 0) { rs[0] = a; rq[0] = b; }
    }
    __syncthreads();
    float mean = rs[0] * (1.0f / D_);
    float var  = rq[0] * (1.0f / D_) - mean * mean;
    float inv  = rsqrtf(var + 1e-5f);
    for (int i = tid; i < D_; i += 256)
        out[(size_t)row * D_ + i] = (x[i] - mean) * inv * sc[i] + bi[i];
}

__global__ void softmax_k(float* __restrict__ att) {
    size_t row = blockIdx.x;
    int i = (int)(row & (S_ - 1));
    float* p = att + row * (size_t)S_;
    int n = i + 1;
    int tid = threadIdx.x;
    __shared__ float red[8];
    float m = -3.4e38f;
    for (int j = tid; j < n; j += 256) m = fmaxf(m, p[j]);
    #pragma unroll
    for (int o = 16; o > 0; o >>= 1) m = fmaxf(m, __shfl_xor_sync(0xffffffffu, m, o));
    if ((tid & 31) == 0) red[tid >> 5] = m;
    __syncthreads();
    if (tid < 32) {
        float t = (tid < 8) ? red[tid] : -3.4e38f;
        #pragma unroll
        for (int o = 4; o > 0; o >>= 1) t = fmaxf(t, __shfl_xor_sync(0xffffffffu, t, o));
        if (tid == 0) red[0] = t;
    }
    __syncthreads();
    m = red[0];
    float sum = 0.f;
    for (int j = tid; j < n; j += 256) { float e = __expf(p[j] - m); p[j] = e; sum += e; }
    __syncthreads();
    #pragma unroll
    for (int o = 16; o > 0; o >>= 1) sum += __shfl_xor_sync(0xffffffffu, sum, o);
    if ((tid & 31) == 0) red[tid >> 5] = sum;
    __syncthreads();
    if (tid < 32) {
        float t = (tid < 8) ? red[tid] : 0.f;
        #pragma unroll
        for (int o = 4; o > 0; o >>= 1) t += __shfl_xor_sync(0xffffffffu, t, o);
        if (tid == 0) red[0] = t;
    }
    __syncthreads();
    float inv = 1.0f / red[0];
    for (int j = tid; j < n; j += 256) p[j] *= inv;
    for (int j = n + tid; j < S_; j += 256) p[j] = 0.f;
}

__global__ void transpose_k(const float* __restrict__ in, float* __restrict__ out,
                            int R, int C, int ldi, int ldo,
                            int nz2, long sI1, long sI2, long sO1, long sO2)
{
    int z = blockIdx.z, z1 = z / nz2, z2 = z - z1 * nz2;
    in  += z1 * sI1 + z2 * sI2;
    out += z1 * sO1 + z2 * sO2;
    __shared__ float t[32][33];
    int c0 = blockIdx.x * 32, r0 = blockIdx.y * 32;
    int x = threadIdx.x, y = threadIdx.y;
    #pragma unroll
    for (int i = 0; i < 32; i += 8) {
        int r = r0 + y + i;
        if (r < R && c0 + x < C) t[y + i][x] = in[(size_t)r * ldi + c0 + x];
    }
    __syncthreads();
    #pragma unroll
    for (int i = 0; i < 32; i += 8) {
        int c = c0 + y + i;
        if (c < C && r0 + x < R) out[(size_t)c * ldo + r0 + x] = t[x][y + i];
    }
}

__global__ void packb_k(const float* __restrict__ bq, const float* __restrict__ bk,
                        const float* __restrict__ bv) {
    int i = blockIdx.x * 256 + threadIdx.x;
    if (i >= NL_ * 3 * D_) return;
    int l = i / (3 * D_), r = i - l * 3 * D_;
    float v = (r < D_) ? bq[l * D_ + r] : (r < 2 * D_) ? bk[l * D_ + r - D_] : bv[l * D_ + r - 2 * D_];
    g_bqkv[i] = v;
}

// ============ launch helpers ============
template<bool RELU, bool RESID, bool BIAS, bool CAUSAL>
static void tc_gemm(const float* A, const float* B, const float* bias, const float* Cin, float* C,
                    int M, int N, int K, int lda, int ldb, int ldc, float alpha = 1.f,
                    int Z = 1, int nz2 = 1,
                    long sA1 = 0, long sA2 = 0, long sB1 = 0, long sB2 = 0,
                    long sC1 = 0, long sC2 = 0)
{
    dim3 grid(cdiv(N, BN), cdiv(M, BM), Z);
    gemm_mma<RELU, RESID, BIAS, CAUSAL><<<grid, 256>>>(
        A, B, bias, Cin, C, M, N, K, lda, ldb, ldc,
        nz2, sA1, sA2, sB1, sB2, sC1, sC2, alpha);
}

static void tr(const float* in, float* out, int R, int C, int ldi, int ldo,
               int Z, int nz2, long sI1, long sI2, long sO1, long sO2)
{
    dim3 grid(cdiv(C, 32), cdiv(R, 32), Z);
    transpose_k<<<grid, dim3(32, 8)>>>(in, out, R, C, ldi, ldo, nz2, sI1, sI2, sO1, sO2);
}

// ============ orchestration ============
extern "C" void kernel_launch(void* const* d_in, const int* in_sizes, int n_in,
                              void* d_out, int out_size) {
    const int*   idx   = (const int*)  d_in[0];
    const float* emb   = (const float*)d_in[1];
    const float* cls_b = (const float*)d_in[2];
    const float* ln1_s = (const float*)d_in[3];
    const float* ln1_b = (const float*)d_in[4];
    const float* wq    = (const float*)d_in[5];
    const float* bq    = (const float*)d_in[6];
    const float* wk    = (const float*)d_in[7];
    const float* bk    = (const float*)d_in[8];
    const float* wv    = (const float*)d_in[9];
    const float* bv    = (const float*)d_in[10];
    const float* wo    = (const float*)d_in[11];
    const float* bo    = (const float*)d_in[12];
    const float* ln2_s = (const float*)d_in[13];
    const float* ln2_b = (const float*)d_in[14];
    const float* w1    = (const float*)d_in[15];
    const float* b1    = (const float*)d_in[16];
    const float* w2    = (const float*)d_in[17];
    const float* b2    = (const float*)d_in[18];
    const float* lnf_s = (const float*)d_in[19];
    const float* lnf_b = (const float*)d_in[20];
    float* out = (float*)d_out;

    float *gx, *gh, *gqkv, *go, *gff, *gatt, *gvT, *gwqkv, *gwoT, *gw1T, *gw2T, *gbq;
    cudaGetSymbolAddress((void**)&gx,   g_x);
    cudaGetSymbolAddress((void**)&gh,   g_h);
    cudaGetSymbolAddress((void**)&gqkv, g_qkv);
    cudaGetSymbolAddress((void**)&go,   g_o);
    cudaGetSymbolAddress((void**)&gff,  g_ff);
    cudaGetSymbolAddress((void**)&gatt, g_att);
    cudaGetSymbolAddress((void**)&gvT,  g_vT);
    cudaGetSymbolAddress((void**)&gwqkv,g_wqkv);
    cudaGetSymbolAddress((void**)&gwoT, g_woT);
    cudaGetSymbolAddress((void**)&gw1T, g_w1T);
    cudaGetSymbolAddress((void**)&gw2T, g_w2T);
    cudaGetSymbolAddress((void**)&gbq,  g_bqkv);

    // weight repack to K-major [N,K]
    tr(wq, gwqkv,                   D_, DH_, DH_, D_, NL_*H_, H_,
       (long)H_*D_*DH_, (long)D_*DH_, (long)3*D_*D_, (long)DH_*D_);
    tr(wk, gwqkv + (size_t)D_*D_,   D_, DH_, DH_, D_, NL_*H_, H_,
       (long)H_*D_*DH_, (long)D_*DH_, (long)3*D_*D_, (long)DH_*D_);
    tr(wv, gwqkv + (size_t)2*D_*D_, D_, DH_, DH_, D_, NL_*H_, H_,
       (long)H_*D_*DH_, (long)D_*DH_, (long)3*D_*D_, (long)DH_*D_);
    tr(wo, gwoT, D_, D_, D_, D_, NL_, 1, (long)D_*D_, 0, (long)D_*D_, 0);
    tr(w1, gw1T, D_, DFF_, DFF_, D_, NL_, 1, (long)D_*DFF_, 0, (long)DFF_*D_, 0);
    tr(w2, gw2T, DFF_, D_, D_, DFF_, NL_, 1, (long)DFF_*D_, 0, (long)D_*DFF_, 0);
    packb_k<<<cdiv(NL_*3*D_, 256), 256>>>(bq, bk, bv);

    embed_k<<<cdiv(BSZ_*D_, 256), 256>>>(idx, emb);

    for (int l = 0; l < NL_; l++) {
        ln_k<<<BSZ_, 256>>>(gx, gh, ln1_s + l*D_, ln1_b + l*D_);

        // qkv: [2048,1024] @ [3072,1024]^T
        tc_gemm<false,false,true,false>(gh, gwqkv + (size_t)l*3*D_*D_, gbq + l*3*D_, nullptr, gqkv,
                                        BSZ_, 3*D_, D_, D_, D_, 3*D_);

        // scores = 1/8 * q @ k^T per (b,h), causal tile skip
        tc_gemm<false,false,false,true>(gqkv, gqkv + D_, nullptr, nullptr, gatt,
                                        S_, S_, DH_, 3*D_, 3*D_, S_, 0.125f,
                                        NB_*H_, H_,
                                        (long)S_*3*D_, DH_, (long)S_*3*D_, DH_,
                                        (long)H_*S_*S_, (long)S_*S_);

        softmax_k<<<NB_*H_*S_, 256>>>(gatt);

        // V^T per (b,h)
        tr(gqkv + 2*D_, gvT, S_, DH_, 3*D_, S_, NB_*H_, H_,
           (long)S_*3*D_, DH_, (long)H_*DH_*S_, (long)DH_*S_);

        // o = P @ (V^T)^T
        tc_gemm<false,false,false,false>(gatt, gvT, nullptr, nullptr, go,
                                         S_, DH_, S_, S_, S_, D_, 1.f,
                                         NB_*H_, H_,
                                         (long)H_*S_*S_, (long)S_*S_,
                                         (long)H_*DH_*S_, (long)DH_*S_,
                                         (long)S_*D_, DH_);

        // x += o @ wo^T + bo
        tc_gemm<false,true,true,false>(go, gwoT + (size_t)l*D_*D_, bo + l*D_, gx, gx,
                                       BSZ_, D_, D_, D_, D_, D_);

        ln_k<<<BSZ_, 256>>>(gx, gh, ln2_s + l*D_, ln2_b + l*D_);

        tc_gemm<true,false,true,false>(gh, gw1T + (size_t)l*DFF_*D_, b1 + l*DFF_, nullptr, gff,
                                       BSZ_, DFF_, D_, D_, D_, DFF_);
        tc_gemm<false,true,true,false>(gff, gw2T + (size_t)l*D_*DFF_, b2 + l*D_, gx, gx,
                                       BSZ_, D_, DFF_, DFF_, DFF_, D_);
    }

    ln_k<<<BSZ_, 256>>>(gx, gh, lnf_s, lnf_b);

    tc_gemm<false,false,true,false>(gh, emb, cls_b, nullptr, out,
                                    BSZ_, V_, D_, D_, D_, V_);
}

// round 5
// speedup vs baseline: 3.4198x; 1.1931x over previous
#include <cuda_runtime.h>
#include <math.h>
#include <cstdint>

// ---------------- problem constants ----------------
#define D_   1024
#define H_   16
#define DH_  64
#define NL_  4
#define DFF_ 4096
#define V_   32000
#define S_   1024
#define NB_  2
#define BSZ_ (NB_*S_)

static inline int cdiv(int a, int b) { return (a + b - 1) / b; }

// ---------------- scratch ----------------
__device__ float g_x   [BSZ_*D_];
__device__ float g_h   [BSZ_*D_];
__device__ float g_qkv [BSZ_*3*D_];
__device__ float g_o   [BSZ_*D_];
__device__ float g_ff  [BSZ_*DFF_];
__device__ float g_att [(size_t)NB_*H_*S_*S_];
__device__ float g_vT  [(size_t)NB_*H_*DH_*S_];
__device__ float g_wqkv[(size_t)NL_*3*D_*D_];
__device__ float g_woT [(size_t)NL_*D_*D_];
__device__ float g_w1T [(size_t)NL_*DFF_*D_];
__device__ float g_w2T [(size_t)NL_*D_*DFF_];
__device__ float g_bqkv[NL_*3*D_];
__device__ float g_embr[(size_t)V_*D_];     // tf32-rounded classifier weight

// ---------------- tf32 / mma helpers ----------------
__device__ __forceinline__ float tf32r(float x) {
    uint32_t u;
    asm("cvt.rna.tf32.f32 %0, %1;" : "=r"(u) : "f"(x));
    return __uint_as_float(u);
}
__device__ __forceinline__ void mma1688(float* d, const uint32_t* a, const uint32_t* b) {
    asm volatile(
        "mma.sync.aligned.m16n8k8.row.col.f32.tf32.tf32.f32 "
        "{%0,%1,%2,%3}, {%4,%5,%6,%7}, {%8,%9}, {%0,%1,%2,%3};"
        : "+f"(d[0]), "+f"(d[1]), "+f"(d[2]), "+f"(d[3])
        : "r"(a[0]), "r"(a[1]), "r"(a[2]), "r"(a[3]), "r"(b[0]), "r"(b[1]));
}
__device__ __forceinline__ uint32_t smem_u32(const void* p) {
    uint32_t a;
    asm("{ .reg .u64 t; cvta.to.shared.u64 t, %1; cvt.u32.u64 %0, t; }" : "=r"(a) : "l"(p));
    return a;
}
__device__ __forceinline__ void cpa16(uint32_t dst, const float* src, bool pred) {
    int sz = pred ? 16 : 0;
    asm volatile("cp.async.cg.shared.global [%0], [%1], 16, %2;"
                 :: "r"(dst), "l"(src), "r"(sz) : "memory");
}
#define CPA_COMMIT() asm volatile("cp.async.commit_group;" ::: "memory")
#define CPA_WAIT1()  asm volatile("cp.async.wait_group 1;" ::: "memory")

// ============ tf32 mma.sync GEMM, cp.async 3-stage, 64x64 warp tiles ============
// C = alpha * A @ B^T (+bias)(+Cin)(relu)(tf32-round); A [M,K] rm, B [N,K] K-major.
constexpr int BM = 128, BN = 128, BK = 32, LDS_ = 36;
constexpr int STAGE_F = 2 * BM * LDS_;            // floats per stage (A+B)
constexpr int NSTAGE = 3;
constexpr int SMEM_DYN = NSTAGE * STAGE_F * 4;    // 110592 B

template<bool RELU, bool RESID, bool BIAS, bool CAUSAL, bool ROUND>
__global__ void __launch_bounds__(128) gemm_mma(
    const float* __restrict__ Ag, const float* __restrict__ Bg,
    const float* __restrict__ biasg, const float* __restrict__ Cing,
    float* __restrict__ Cg,
    int M, int N, int K, int lda, int ldb, int ldc,
    int nz2, long sA1, long sA2, long sB1, long sB2, long sC1, long sC2,
    float alpha)
{
    int row0 = blockIdx.y * BM;
    int col0 = blockIdx.x * BN;
    if (CAUSAL && col0 > row0 + BM - 1) return;

    int z = blockIdx.z, z1 = z / nz2, z2 = z - z1 * nz2;
    const float* A   = Ag + z1 * sA1 + z2 * sA2;
    const float* B   = Bg + z1 * sB1 + z2 * sB2;
    float*       C   = Cg + z1 * sC1 + z2 * sC2;
    const float* Cin = RESID ? (Cing + z1 * sC1 + z2 * sC2) : nullptr;

    extern __shared__ float sm[];
    uint32_t sm0 = smem_u32(sm);

    int tid = threadIdx.x;
    int wid = tid >> 5, lane = tid & 31;
    int wm = wid >> 1, wn = wid & 1;          // 2x2 warps, 64x64 each
    int gid = lane >> 2, tig = lane & 3;

    // cp.async coords for this thread: 16 chunks (8 A + 8 B)
    int cr = tid >> 3;                        // row 0..15 step base
    int cc = (tid & 7) * 4;                   // float col within BK
    // rows handled: cr, cr+16, ..., cr+112  (8 rows)

    float acc[4][8][4];
    #pragma unroll
    for (int a = 0; a < 4; a++)
        #pragma unroll
        for (int b = 0; b < 8; b++)
            #pragma unroll
            for (int c = 0; c < 4; c++) acc[a][b][c] = 0.f;

    int KT = K / BK;

    auto issue = [&](int kt, int slot) {
        int k0 = kt * BK;
        uint32_t abase = sm0 + (uint32_t)slot * STAGE_F * 4;
        uint32_t bbase = abase + BM * LDS_ * 4;
        #pragma unroll
        for (int i = 0; i < 8; i++) {
            int r = cr + i * 16;
            int gm = row0 + r;
            const float* pa = A + (size_t)(gm < M ? gm : 0) * lda + k0 + cc;
            cpa16(abase + (r * LDS_ + cc) * 4, pa, gm < M);
            int gn = col0 + r;
            const float* pb = B + (size_t)(gn < N ? gn : 0) * ldb + k0 + cc;
            cpa16(bbase + (r * LDS_ + cc) * 4, pb, gn < N);
        }
    };

    int nPre = KT < (NSTAGE - 1) ? KT : (NSTAGE - 1);
    for (int p = 0; p < nPre; p++) { issue(p, p); CPA_COMMIT(); }

    for (int kt = 0; kt < KT; kt++) {
        CPA_WAIT1();
        __syncthreads();
        int nxt = kt + NSTAGE - 1;
        if (nxt < KT) issue(nxt, nxt % NSTAGE);
        CPA_COMMIT();

        const float* As = sm + (kt % NSTAGE) * STAGE_F;
        const float* Bs = As + BM * LDS_;
        const float* Ab = As + (wm * 64 + gid) * LDS_;
        const float* Bb = Bs + (wn * 64 + gid) * LDS_;

        #pragma unroll
        for (int ks = 0; ks < 4; ks++) {
            int kc = ks * 8 + tig;
            uint32_t af[4][4], bf[8][2];
            #pragma unroll
            for (int mt = 0; mt < 4; mt++) {
                const float* p = Ab + mt * 16 * LDS_;
                af[mt][0] = __float_as_uint(p[kc]);
                af[mt][1] = __float_as_uint(p[8 * LDS_ + kc]);
                af[mt][2] = __float_as_uint(p[kc + 4]);
                af[mt][3] = __float_as_uint(p[8 * LDS_ + kc + 4]);
            }
            #pragma unroll
            for (int nt = 0; nt < 8; nt++) {
                const float* p = Bb + nt * 8 * LDS_;
                bf[nt][0] = __float_as_uint(p[kc]);
                bf[nt][1] = __float_as_uint(p[kc + 4]);
            }
            #pragma unroll
            for (int mt = 0; mt < 4; mt++)
                #pragma unroll
                for (int nt = 0; nt < 8; nt++)
                    mma1688(acc[mt][nt], af[mt], bf[nt]);
        }
    }

    // ---------------- epilogue ----------------
    #pragma unroll
    for (int mt = 0; mt < 4; mt++) {
        #pragma unroll
        for (int half = 0; half < 2; half++) {
            int gm = row0 + wm * 64 + mt * 16 + gid + half * 8;
            if (gm >= M) continue;
            #pragma unroll
            for (int nt = 0; nt < 8; nt++) {
                int gn = col0 + wn * 64 + nt * 8 + 2 * tig;
                if (gn >= N) continue;
                float v0 = acc[mt][nt][half * 2 + 0] * alpha;
                float v1 = acc[mt][nt][half * 2 + 1] * alpha;
                if (BIAS)  { v0 += biasg[gn]; v1 += biasg[gn + 1]; }
                if (RESID) {
                    const float* ci = Cin + (size_t)gm * ldc + gn;
                    v0 += ci[0]; v1 += ci[1];
                }
                if (RELU) { v0 = fmaxf(v0, 0.f); v1 = fmaxf(v1, 0.f); }
                if (ROUND) { v0 = tf32r(v0); v1 = tf32r(v1); }
                *(float2*)(C + (size_t)gm * ldc + gn) = make_float2(v0, v1);
            }
        }
    }
}

// ============ auxiliary kernels ============
__global__ void embed_k(const int* __restrict__ idx, const float* __restrict__ emb) {
    int t = blockIdx.x * blockDim.x + threadIdx.x;
    if (t >= BSZ_ * D_) return;
    int d = t & (D_ - 1);
    int bs = t >> 10;
    int s = bs & (S_ - 1);
    int tok = idx[bs];
    int i2 = d & ~1;
    float freq = __expf((float)i2 * (-9.210340371976184f / (float)D_));
    float ang = (float)s * freq;
    float pe = (d & 1) ? cosf(ang) : sinf(ang);
    g_x[t] = emb[(size_t)tok * D_ + d] * 32.0f + pe;
}

__global__ void roundcpy_k(const float* __restrict__ in, float* __restrict__ out, size_t n) {
    size_t i = (size_t)blockIdx.x * blockDim.x + threadIdx.x;
    if (i < n) out[i] = tf32r(in[i]);
}

__global__ void ln_k(const float* __restrict__ in, float* __restrict__ out,
                     const float* __restrict__ sc, const float* __restrict__ bi) {
    int row = blockIdx.x;
    const float* x = in + (size_t)row * D_;
    int tid = threadIdx.x;
    float s = 0.f, ss = 0.f;
    for (int i = tid; i < D_; i += 256) { float v = x[i]; s += v; ss = fmaf(v, v, ss); }
    __shared__ float rs[8], rq[8];
    #pragma unroll
    for (int o = 16; o > 0; o >>= 1) {
        s  += __shfl_xor_sync(0xffffffffu, s,  o);
        ss += __shfl_xor_sync(0xffffffffu, ss, o);
    }
    if ((tid & 31) == 0) { rs[tid >> 5] = s; rq[tid >> 5] = ss; }
    __syncthreads();
    if (tid < 32) {
        float a = (tid < 8) ? rs[tid] : 0.f;
        float b = (tid < 8) ? rq[tid] : 0.f;
        #pragma unroll
        for (int o = 4; o > 0; o >>= 1) {
            a += __shfl_xor_sync(0xffffffffu, a, o);
            b += __shfl_xor_sync(0xffffffffu, b, o);
        }
        if (tid == 0) { rs[0] = a; rq[0] = b; }
    }
    __syncthreads();
    float mean = rs[0] * (1.0f / D_);
    float var  = rq[0] * (1.0f / D_) - mean * mean;
    float inv  = rsqrtf(var + 1e-5f);
    for (int i = tid; i < D_; i += 256)
        out[(size_t)row * D_ + i] = tf32r((x[i] - mean) * inv * sc[i] + bi[i]);
}

// final LN: no tf32 rounding of the residual-normed activations used by classifier?
// classifier A must be rounded too (it is a GEMM input) -> same kernel is fine.

__global__ void softmax_k(float* __restrict__ att) {
    size_t row = blockIdx.x;
    int i = (int)(row & (S_ - 1));
    float* p = att + row * (size_t)S_;
    int n = i + 1;
    int tid = threadIdx.x;
    __shared__ float red[8];
    float m = -3.4e38f;
    for (int j = tid; j < n; j += 256) m = fmaxf(m, p[j]);
    #pragma unroll
    for (int o = 16; o > 0; o >>= 1) m = fmaxf(m, __shfl_xor_sync(0xffffffffu, m, o));
    if ((tid & 31) == 0) red[tid >> 5] = m;
    __syncthreads();
    if (tid < 32) {
        float t = (tid < 8) ? red[tid] : -3.4e38f;
        #pragma unroll
        for (int o = 4; o > 0; o >>= 1) t = fmaxf(t, __shfl_xor_sync(0xffffffffu, t, o));
        if (tid == 0) red[0] = t;
    }
    __syncthreads();
    m = red[0];
    float sum = 0.f;
    for (int j = tid; j < n; j += 256) { float e = __expf(p[j] - m); p[j] = e; sum += e; }
    __syncthreads();
    #pragma unroll
    for (int o = 16; o > 0; o >>= 1) sum += __shfl_xor_sync(0xffffffffu, sum, o);
    if ((tid & 31) == 0) red[tid >> 5] = sum;
    __syncthreads();
    if (tid < 32) {
        float t = (tid < 8) ? red[tid] : 0.f;
        #pragma unroll
        for (int o = 4; o > 0; o >>= 1) t += __shfl_xor_sync(0xffffffffu, t, o);
        if (tid == 0) red[0] = t;
    }
    __syncthreads();
    float inv = 1.0f / red[0];
    for (int j = tid; j < n; j += 256) p[j] = tf32r(p[j] * inv);
    for (int j = n + tid; j < S_; j += 256) p[j] = 0.f;
}

__global__ void transpose_k(const float* __restrict__ in, float* __restrict__ out,
                            int R, int C, int ldi, int ldo,
                            int nz2, long sI1, long sI2, long sO1, long sO2)
{
    int z = blockIdx.z, z1 = z / nz2, z2 = z - z1 * nz2;
    in  += z1 * sI1 + z2 * sI2;
    out += z1 * sO1 + z2 * sO2;
    __shared__ float t[32][33];
    int c0 = blockIdx.x * 32, r0 = blockIdx.y * 32;
    int x = threadIdx.x, y = threadIdx.y;
    #pragma unroll
    for (int i = 0; i < 32; i += 8) {
        int r = r0 + y + i;
        if (r < R && c0 + x < C) t[y + i][x] = in[(size_t)r * ldi + c0 + x];
    }
    __syncthreads();
    #pragma unroll
    for (int i = 0; i < 32; i += 8) {
        int c = c0 + y + i;
        if (c < C && r0 + x < R) out[(size_t)c * ldo + r0 + x] = tf32r(t[x][y + i]);
    }
}

__global__ void packb_k(const float* __restrict__ bq, const float* __restrict__ bk,
                        const float* __restrict__ bv) {
    int i = blockIdx.x * 256 + threadIdx.x;
    if (i >= NL_ * 3 * D_) return;
    int l = i / (3 * D_), r = i - l * 3 * D_;
    float v = (r < D_) ? bq[l * D_ + r] : (r < 2 * D_) ? bk[l * D_ + r - D_] : bv[l * D_ + r - 2 * D_];
    g_bqkv[i] = v;
}

// ============ launch helpers ============
template<bool RELU, bool RESID, bool BIAS, bool CAUSAL, bool ROUND>
static void tc_gemm(const float* A, const float* B, const float* bias, const float* Cin, float* C,
                    int M, int N, int K, int lda, int ldb, int ldc, float alpha = 1.f,
                    int Z = 1, int nz2 = 1,
                    long sA1 = 0, long sA2 = 0, long sB1 = 0, long sB2 = 0,
                    long sC1 = 0, long sC2 = 0)
{
    cudaFuncSetAttribute(gemm_mma<RELU, RESID, BIAS, CAUSAL, ROUND>,
                         cudaFuncAttributeMaxDynamicSharedMemorySize, SMEM_DYN);
    dim3 grid(cdiv(N, BN), cdiv(M, BM), Z);
    gemm_mma<RELU, RESID, BIAS, CAUSAL, ROUND><<<grid, 128, SMEM_DYN>>>(
        A, B, bias, Cin, C, M, N, K, lda, ldb, ldc,
        nz2, sA1, sA2, sB1, sB2, sC1, sC2, alpha);
}

static void tr(const float* in, float* out, int R, int C, int ldi, int ldo,
               int Z, int nz2, long sI1, long sI2, long sO1, long sO2)
{
    dim3 grid(cdiv(C, 32), cdiv(R, 32), Z);
    transpose_k<<<grid, dim3(32, 8)>>>(in, out, R, C, ldi, ldo, nz2, sI1, sI2, sO1, sO2);
}

// ============ orchestration ============
extern "C" void kernel_launch(void* const* d_in, const int* in_sizes, int n_in,
                              void* d_out, int out_size) {
    const int*   idx   = (const int*)  d_in[0];
    const float* emb   = (const float*)d_in[1];
    const float* cls_b = (const float*)d_in[2];
    const float* ln1_s = (const float*)d_in[3];
    const float* ln1_b = (const float*)d_in[4];
    const float* wq    = (const float*)d_in[5];
    const float* bq    = (const float*)d_in[6];
    const float* wk    = (const float*)d_in[7];
    const float* bk    = (const float*)d_in[8];
    const float* wv    = (const float*)d_in[9];
    const float* bv    = (const float*)d_in[10];
    const float* wo    = (const float*)d_in[11];
    const float* bo    = (const float*)d_in[12];
    const float* ln2_s = (const float*)d_in[13];
    const float* ln2_b = (const float*)d_in[14];
    const float* w1    = (const float*)d_in[15];
    const float* b1    = (const float*)d_in[16];
    const float* w2    = (const float*)d_in[17];
    const float* b2    = (const float*)d_in[18];
    const float* lnf_s = (const float*)d_in[19];
    const float* lnf_b = (const float*)d_in[20];
    float* out = (float*)d_out;

    float *gx, *gh, *gqkv, *go, *gff, *gatt, *gvT, *gwqkv, *gwoT, *gw1T, *gw2T, *gbq, *gembr;
    cudaGetSymbolAddress((void**)&gx,   g_x);
    cudaGetSymbolAddress((void**)&gh,   g_h);
    cudaGetSymbolAddress((void**)&gqkv, g_qkv);
    cudaGetSymbolAddress((void**)&go,   g_o);
    cudaGetSymbolAddress((void**)&gff,  g_ff);
    cudaGetSymbolAddress((void**)&gatt, g_att);
    cudaGetSymbolAddress((void**)&gvT,  g_vT);
    cudaGetSymbolAddress((void**)&gwqkv,g_wqkv);
    cudaGetSymbolAddress((void**)&gwoT, g_woT);
    cudaGetSymbolAddress((void**)&gw1T, g_w1T);
    cudaGetSymbolAddress((void**)&gw2T, g_w2T);
    cudaGetSymbolAddress((void**)&gbq,  g_bqkv);
    cudaGetSymbolAddress((void**)&gembr,g_embr);

    // weight repack to K-major [N,K] (tf32-rounded)
    tr(wq, gwqkv,                   D_, DH_, DH_, D_, NL_*H_, H_,
       (long)H_*D_*DH_, (long)D_*DH_, (long)3*D_*D_, (long)DH_*D_);
    tr(wk, gwqkv + (size_t)D_*D_,   D_, DH_, DH_, D_, NL_*H_, H_,
       (long)H_*D_*DH_, (long)D_*DH_, (long)3*D_*D_, (long)DH_*D_);
    tr(wv, gwqkv + (size_t)2*D_*D_, D_, DH_, DH_, D_, NL_*H_, H_,
       (long)H_*D_*DH_, (long)D_*DH_, (long)3*D_*D_, (long)DH_*D_);
    tr(wo, gwoT, D_, D_, D_, D_, NL_, 1, (long)D_*D_, 0, (long)D_*D_, 0);
    tr(w1, gw1T, D_, DFF_, DFF_, D_, NL_, 1, (long)D_*DFF_, 0, (long)DFF_*D_, 0);
    tr(w2, gw2T, DFF_, D_, D_, DFF_, NL_, 1, (long)DFF_*D_, 0, (long)D_*DFF_, 0);
    packb_k<<<cdiv(NL_*3*D_, 256), 256>>>(bq, bk, bv);
    roundcpy_k<<<cdiv(V_*D_, 256), 256>>>(emb, gembr, (size_t)V_*D_);

    embed_k<<<cdiv(BSZ_*D_, 256), 256>>>(idx, emb);

    for (int l = 0; l < NL_; l++) {
        ln_k<<<BSZ_, 256>>>(gx, gh, ln1_s + l*D_, ln1_b + l*D_);

        // qkv: [2048,1024] @ [3072,1024]^T  (round: q,k,v feed attention GEMMs)
        tc_gemm<false,false,true,false,true>(gh, gwqkv + (size_t)l*3*D_*D_, gbq + l*3*D_, nullptr, gqkv,
                                             BSZ_, 3*D_, D_, D_, D_, 3*D_);

        // scores = 1/8 * q @ k^T per (b,h), causal tile skip
        tc_gemm<false,false,false,true,false>(gqkv, gqkv + D_, nullptr, nullptr, gatt,
                                              S_, S_, DH_, 3*D_, 3*D_, S_, 0.125f,
                                              NB_*H_, H_,
                                              (long)S_*3*D_, DH_, (long)S_*3*D_, DH_,
                                              (long)H_*S_*S_, (long)S_*S_);

        softmax_k<<<NB_*H_*S_, 256>>>(gatt);

        // V^T per (b,h)
        tr(gqkv + 2*D_, gvT, S_, DH_, 3*D_, S_, NB_*H_, H_,
           (long)S_*3*D_, DH_, (long)H_*DH_*S_, (long)DH_*S_);

        // o = P @ (V^T)^T  (round: feeds O-proj)
        tc_gemm<false,false,false,false,true>(gatt, gvT, nullptr, nullptr, go,
                                              S_, DH_, S_, S_, S_, D_, 1.f,
                                              NB_*H_, H_,
                                              (long)H_*S_*S_, (long)S_*S_,
                                              (long)H_*DH_*S_, (long)DH_*S_,
                                              (long)S_*D_, DH_);

        // x += o @ wo^T + bo (full fp32 residual)
        tc_gemm<false,true,true,false,false>(go, gwoT + (size_t)l*D_*D_, bo + l*D_, gx, gx,
                                             BSZ_, D_, D_, D_, D_, D_);

        ln_k<<<BSZ_, 256>>>(gx, gh, ln2_s + l*D_, ln2_b + l*D_);

        // ff = relu(h @ w1 + b1)  (round: feeds FFN2)
        tc_gemm<true,false,true,false,true>(gh, gw1T + (size_t)l*DFF_*D_, b1 + l*DFF_, nullptr, gff,
                                            BSZ_, DFF_, D_, D_, D_, DFF_);
        // x += ff @ w2 + b2
        tc_gemm<false,true,true,false,false>(gff, gw2T + (size_t)l*D_*DFF_, b2 + l*D_, gx, gx,
                                             BSZ_, D_, DFF_, DFF_, DFF_, D_);
    }

    ln_k<<<BSZ_, 256>>>(gx, gh, lnf_s, lnf_b);

    // logits = h @ emb^T + cls_b
    tc_gemm<false,false,true,false,false>(gh, gembr, cls_b, nullptr, out,
                                          BSZ_, V_, D_, D_, D_, V_);
}